// round 16
// baseline (speedup 1.0000x reference)
#include <cuda_runtime.h>
#include <cuda_bf16.h>

// CasamentoMult on GB300 — FINAL: best-measured form (R4: 14.75us, rel_err 0)
// consolidated to a SINGLE full wave (592 blocks @ 4 resident/SM) to drop the
// 2nd-wave transition overhead.
// sigma = 1/sqrt(2*pi) => log_sqrt_pi == 0; pair term = exp(-pi*diff^2).
// With values prescaled by c = sqrt(pi*log2(e)), each term is
//   exp(-pi*x^2) = 2^(-(c*x)^2) = ex2(-(u1-u0)^2)   on prescaled u.
// The [2, N-2] Toeplitz MMD collapses (diagonals -> NE; cross-diagonals
// telescope) to:
//  total = NE + sum_k [ 0.5*(e(y1-y0)+e(d1-d0)-e(d1-y0)-e(d0-y1)) - e(d0-y0) ]
//             + 0.5*e(d[0]-y[0]) - 0.5*e(d[NE]-y[NE]),   NE = N-2.
//
// 15-round conclusion: at the harness's replay-loop clock the 20M scalar
// exponentials are the irreducible wall (~14.5us); every pipe-rebalance,
// packing, occupancy, and MLP variant lands on the same time or worse.

#define NBLK 592           // 148 SMs * 4 resident blocks -> exactly one wave
#define NTHR 256

__device__ float    g_partials[NBLK];
__device__ unsigned g_ticket = 0;

#define SC 2.1289340388624523f   // sqrt(pi * log2(e))

__device__ __forceinline__ float ex2neg(float u) {
    // 2^(-u*u); operand negation folds into the FMUL.
    float a = -u * u;
    float r;
    asm("ex2.approx.f32 %0, %1;" : "=f"(r) : "f"(a));
    return r;
}

// Raw (unscaled) version for the tail/boundary terms.
__device__ __forceinline__ float gex_raw(float x) {
    return ex2neg(x * SC);
}

// One element on PRESCALED values.
__device__ __forceinline__ void term(float& accA, float& accS,
                                     float D0, float D1, float Y0, float Y1) {
    float gy = ex2neg(Y1 - Y0);
    float gd = ex2neg(D1 - D0);
    float c1 = ex2neg(D1 - Y0);
    float c2 = ex2neg(D0 - Y1);
    float s  = ex2neg(D0 - Y0);
    accA += (gy + gd) - (c1 + c2);
    accS += s;
}

__global__ void __launch_bounds__(NTHR, 4)
casa_fused(const float* __restrict__ d, const float* __restrict__ y,
           int NE, int ngroups, float* __restrict__ out) {
    float aA0 = 0.f, aA1 = 0.f, aA2 = 0.f, aA3 = 0.f;
    float aS0 = 0.f, aS1 = 0.f, aS2 = 0.f, aS3 = 0.f;
    const int stride = gridDim.x * blockDim.x;

    for (int g = blockIdx.x * blockDim.x + threadIdx.x; g < ngroups; g += stride) {
        const int base = g << 3;                   // 8 elements per group
        float4 dA = *reinterpret_cast<const float4*>(d + base);
        float4 dB = *reinterpret_cast<const float4*>(d + base + 4);
        float4 yA = *reinterpret_cast<const float4*>(y + base);
        float4 yB = *reinterpret_cast<const float4*>(y + base + 4);
        float d8 = __ldg(d + base + 8) * SC;
        float y8 = __ldg(y + base + 8) * SC;
        dA.x *= SC; dA.y *= SC; dA.z *= SC; dA.w *= SC;
        dB.x *= SC; dB.y *= SC; dB.z *= SC; dB.w *= SC;
        yA.x *= SC; yA.y *= SC; yA.z *= SC; yA.w *= SC;
        yB.x *= SC; yB.y *= SC; yB.z *= SC; yB.w *= SC;

        term(aA0, aS0, dA.x, dA.y, yA.x, yA.y);
        term(aA1, aS1, dA.y, dA.z, yA.y, yA.z);
        term(aA2, aS2, dA.z, dA.w, yA.z, yA.w);
        term(aA3, aS3, dA.w, dB.x, yA.w, yB.x);
        term(aA0, aS0, dB.x, dB.y, yB.x, yB.y);
        term(aA1, aS1, dB.y, dB.z, yB.y, yB.z);
        term(aA2, aS2, dB.z, dB.w, yB.z, yB.w);
        term(aA3, aS3, dB.w, d8,   yB.w, y8);
    }

    float acc = fmaf((aA0 + aA1) + (aA2 + aA3), 0.5f,
                     -((aS0 + aS1) + (aS2 + aS3)));

    // block reduce (float)
    #pragma unroll
    for (int o = 16; o; o >>= 1) acc += __shfl_down_sync(0xffffffffu, acc, o);

    __shared__ float sh[NTHR / 32];
    __shared__ bool  s_last;
    const int lane = threadIdx.x & 31;
    const int w    = threadIdx.x >> 5;
    if (lane == 0) sh[w] = acc;
    __syncthreads();
    if (threadIdx.x == 0) {
        float v = 0.f;
        #pragma unroll
        for (int i = 0; i < NTHR / 32; i++) v += sh[i];
        g_partials[blockIdx.x] = v;
        __threadfence();
        unsigned t = atomicAdd(&g_ticket, 1u);
        s_last = (t == (unsigned)gridDim.x - 1u);
    }
    __syncthreads();
    if (!s_last) return;

    // ---- last block: deterministic double-precision finish ----
    const int tid = threadIdx.x;
    double v = 0.0;
    for (int i = tid; i < NBLK; i += NTHR)       // fixed-order per thread
        v += (double)g_partials[i];

    if (tid == 0) {
        for (int k = 8 * ngroups; k < NE; k++) { // tail (empty when NE%8==0)
            float t0 = d[k], t1 = d[k + 1], u0 = y[k], u1 = y[k + 1];
            float a = gex_raw(u1 - u0) + gex_raw(t1 - t0)
                    - gex_raw(t1 - u0) - gex_raw(t0 - u1);
            v += 0.5 * (double)a - (double)gex_raw(t0 - u0);
        }
        v += 0.5 * ((double)gex_raw(d[0] - y[0]) - (double)gex_raw(d[NE] - y[NE]));
        v += (double)NE;
    }

    #pragma unroll
    for (int o = 16; o; o >>= 1) v += __shfl_down_sync(0xffffffffu, v, o);

    __shared__ double shd[NTHR / 32];
    if (lane == 0) shd[w] = v;
    __syncthreads();
    if (tid == 0) {
        double t = 0.0;
        #pragma unroll
        for (int i = 0; i < NTHR / 32; i++) t += shd[i];
        out[0] = (float)t;
        g_ticket = 0;                  // reset for next graph replay
    }
}

extern "C" void kernel_launch(void* const* d_in, const int* in_sizes, int n_in,
                              void* d_out, int out_size) {
    const float* d = (const float*)d_in[0];
    const float* y = (const float*)d_in[1];
    float* out = (float*)d_out;

    const int n  = in_sizes[0];
    const int NE = n - 2;               // 4,000,000 for N = 4,000,002
    const int ngroups = NE / 8;         // 8 consecutive k per group

    casa_fused<<<NBLK, NTHR>>>(d, y, NE, ngroups, out);
}

// round 17
// speedup vs baseline: 1.1830x; 1.1830x over previous
#include <cuda_runtime.h>
#include <cuda_bf16.h>

// CasamentoMult on GB300 — FINAL (best measured: kernel 13.66us ncu,
// wall 14.75-15.1us across reruns; rel_err 0).
// Single full wave: 592 blocks @ 4 resident/SM.
// sigma = 1/sqrt(2*pi) => log_sqrt_pi == 0; pair term = exp(-pi*diff^2).
// With values prescaled by c = sqrt(pi*log2(e)), each term is
//   exp(-pi*x^2) = 2^(-(c*x)^2) = ex2(-(u1-u0)^2)   on prescaled u.
// The [2, N-2] Toeplitz MMD collapses (diagonals -> NE; cross-diagonals
// telescope) to:
//  total = NE + sum_k [ 0.5*(e(y1-y0)+e(d1-d0)-e(d1-y0)-e(d0-y1)) - e(d0-y0) ]
//             + 0.5*e(d[0]-y[0]) - 0.5*e(d[NE]-y[NE]),   NE = N-2.
//
// 16-round conclusion: at the harness's replay-loop clock the 20M scalar
// exponentials are the irreducible wall (~14.5us); every pipe-rebalance,
// packing, occupancy, and MLP variant lands on the same time or worse.

#define NBLK 592           // 148 SMs * 4 resident blocks -> exactly one wave
#define NTHR 256

__device__ float    g_partials[NBLK];
__device__ unsigned g_ticket = 0;

#define SC 2.1289340388624523f   // sqrt(pi * log2(e))

__device__ __forceinline__ float ex2neg(float u) {
    // 2^(-u*u); operand negation folds into the FMUL.
    float a = -u * u;
    float r;
    asm("ex2.approx.f32 %0, %1;" : "=f"(r) : "f"(a));
    return r;
}

// Raw (unscaled) version for the tail/boundary terms.
__device__ __forceinline__ float gex_raw(float x) {
    return ex2neg(x * SC);
}

// One element on PRESCALED values.
__device__ __forceinline__ void term(float& accA, float& accS,
                                     float D0, float D1, float Y0, float Y1) {
    float gy = ex2neg(Y1 - Y0);
    float gd = ex2neg(D1 - D0);
    float c1 = ex2neg(D1 - Y0);
    float c2 = ex2neg(D0 - Y1);
    float s  = ex2neg(D0 - Y0);
    accA += (gy + gd) - (c1 + c2);
    accS += s;
}

__global__ void __launch_bounds__(NTHR, 4)
casa_fused(const float* __restrict__ d, const float* __restrict__ y,
           int NE, int ngroups, float* __restrict__ out) {
    float aA0 = 0.f, aA1 = 0.f, aA2 = 0.f, aA3 = 0.f;
    float aS0 = 0.f, aS1 = 0.f, aS2 = 0.f, aS3 = 0.f;
    const int stride = gridDim.x * blockDim.x;

    for (int g = blockIdx.x * blockDim.x + threadIdx.x; g < ngroups; g += stride) {
        const int base = g << 3;                   // 8 elements per group
        float4 dA = *reinterpret_cast<const float4*>(d + base);
        float4 dB = *reinterpret_cast<const float4*>(d + base + 4);
        float4 yA = *reinterpret_cast<const float4*>(y + base);
        float4 yB = *reinterpret_cast<const float4*>(y + base + 4);
        float d8 = __ldg(d + base + 8) * SC;
        float y8 = __ldg(y + base + 8) * SC;
        dA.x *= SC; dA.y *= SC; dA.z *= SC; dA.w *= SC;
        dB.x *= SC; dB.y *= SC; dB.z *= SC; dB.w *= SC;
        yA.x *= SC; yA.y *= SC; yA.z *= SC; yA.w *= SC;
        yB.x *= SC; yB.y *= SC; yB.z *= SC; yB.w *= SC;

        term(aA0, aS0, dA.x, dA.y, yA.x, yA.y);
        term(aA1, aS1, dA.y, dA.z, yA.y, yA.z);
        term(aA2, aS2, dA.z, dA.w, yA.z, yA.w);
        term(aA3, aS3, dA.w, dB.x, yA.w, yB.x);
        term(aA0, aS0, dB.x, dB.y, yB.x, yB.y);
        term(aA1, aS1, dB.y, dB.z, yB.y, yB.z);
        term(aA2, aS2, dB.z, dB.w, yB.z, yB.w);
        term(aA3, aS3, dB.w, d8,   yB.w, y8);
    }

    float acc = fmaf((aA0 + aA1) + (aA2 + aA3), 0.5f,
                     -((aS0 + aS1) + (aS2 + aS3)));

    // block reduce (float)
    #pragma unroll
    for (int o = 16; o; o >>= 1) acc += __shfl_down_sync(0xffffffffu, acc, o);

    __shared__ float sh[NTHR / 32];
    __shared__ bool  s_last;
    const int lane = threadIdx.x & 31;
    const int w    = threadIdx.x >> 5;
    if (lane == 0) sh[w] = acc;
    __syncthreads();
    if (threadIdx.x == 0) {
        float v = 0.f;
        #pragma unroll
        for (int i = 0; i < NTHR / 32; i++) v += sh[i];
        g_partials[blockIdx.x] = v;
        __threadfence();
        unsigned t = atomicAdd(&g_ticket, 1u);
        s_last = (t == (unsigned)gridDim.x - 1u);
    }
    __syncthreads();
    if (!s_last) return;

    // ---- last block: deterministic double-precision finish ----
    const int tid = threadIdx.x;
    double v = 0.0;
    for (int i = tid; i < NBLK; i += NTHR)       // fixed-order per thread
        v += (double)g_partials[i];

    if (tid == 0) {
        for (int k = 8 * ngroups; k < NE; k++) { // tail (empty when NE%8==0)
            float t0 = d[k], t1 = d[k + 1], u0 = y[k], u1 = y[k + 1];
            float a = gex_raw(u1 - u0) + gex_raw(t1 - t0)
                    - gex_raw(t1 - u0) - gex_raw(t0 - u1);
            v += 0.5 * (double)a - (double)gex_raw(t0 - u0);
        }
        v += 0.5 * ((double)gex_raw(d[0] - y[0]) - (double)gex_raw(d[NE] - y[NE]));
        v += (double)NE;
    }

    #pragma unroll
    for (int o = 16; o; o >>= 1) v += __shfl_down_sync(0xffffffffu, v, o);

    __shared__ double shd[NTHR / 32];
    if (lane == 0) shd[w] = v;
    __syncthreads();
    if (tid == 0) {
        double t = 0.0;
        #pragma unroll
        for (int i = 0; i < NTHR / 32; i++) t += shd[i];
        out[0] = (float)t;
        g_ticket = 0;                  // reset for next graph replay
    }
}

extern "C" void kernel_launch(void* const* d_in, const int* in_sizes, int n_in,
                              void* d_out, int out_size) {
    const float* d = (const float*)d_in[0];
    const float* y = (const float*)d_in[1];
    float* out = (float*)d_out;

    const int n  = in_sizes[0];
    const int NE = n - 2;               // 4,000,000 for N = 4,000,002
    const int ngroups = NE / 8;         // 8 consecutive k per group

    casa_fused<<<NBLK, NTHR>>>(d, y, NE, ngroups, out);
}